// round 11
// baseline (speedup 1.0000x reference)
#include <cuda_runtime.h>
#include <cuda_bf16.h>

#define B 512
#define T 512
#define C 96

__device__ float g_den[B];
__device__ float g_num[B];
__device__ int g_tag_any;      // any odd 32-bit word nonzero => tags are int32
__device__ int g_mask_byte;    // any mask word > 1 => mask stored as bytes
__device__ int g_not_ones_b;   // (byte mask) some word != 0x01010101
__device__ int g_not_ones_w;   // (int32 mask) some word != 1

__device__ __forceinline__ void unpack2(unsigned long long v, float& lo, float& hi) {
    asm("mov.b64 {%0, %1}, %2;" : "=f"(lo), "=f"(hi) : "l"(v));
}
__device__ __forceinline__ unsigned long long pack2(float lo, float hi) {
    unsigned long long r;
    asm("mov.b64 %0, {%1, %2};" : "=l"(r) : "f"(lo), "f"(hi));
    return r;
}
__device__ __forceinline__ unsigned long long ffma2(unsigned long long a,
                                                    unsigned long long b,
                                                    unsigned long long c) {
    unsigned long long d;
    asm("fma.rn.f32x2 %0, %1, %2, %3;" : "=l"(d) : "l"(a), "l"(b), "l"(c));
    return d;
}
__device__ __forceinline__ unsigned long long fadd2(unsigned long long a,
                                                    unsigned long long b) {
    unsigned long long d;
    asm("add.rn.f32x2 %0, %1, %2;" : "=l"(d) : "l"(a), "l"(b));
    return d;
}
__device__ __forceinline__ float frcp_fast(float x) {
    float r;
    asm("rcp.approx.f32 %0, %1;" : "=f"(r) : "f"(x));
    return r;
}

// ---------------------------------------------------------------------------
// Detection kernels.
__global__ void crf_init_kernel()
{
    g_tag_any = 0; g_mask_byte = 0; g_not_ones_b = 0; g_not_ones_w = 0;
}

__global__ void __launch_bounds__(256) crf_detect_a_kernel(
    const int* __restrict__ t32, const unsigned int* __restrict__ mw)
{
    const int gt = blockIdx.x * 256 + threadIdx.x;
    int ta = 0, mb = 0, nb = 0, nw = 0;
    for (int i = gt; i < 512; i += 64 * 256)
        if (t32[i * 2 + 1] != 0) ta = 1;
    for (int i = gt; i < 65536; i += 64 * 256) {   // first 256 KB: full byte-mask span
        const unsigned int v = mw[i];
        if (v > 1u) mb = 1;
        if (v != 0x01010101u) nb = 1;
        if (v != 1u) nw = 1;
    }
    if (ta) atomicOr(&g_tag_any, 1);
    if (mb) atomicOr(&g_mask_byte, 1);
    if (nb) atomicOr(&g_not_ones_b, 1);
    if (nw) atomicOr(&g_not_ones_w, 1);
}

__global__ void __launch_bounds__(256) crf_detect_b_kernel(
    const unsigned int* __restrict__ mw)
{
    if (g_mask_byte) return;                       // byte mask: buffer is only 256 KB
    const int gt = blockIdx.x * 256 + threadIdx.x;
    int nw = 0;
    for (int i = 65536 + gt; i < 262144; i += 64 * 256)
        if (mw[i] != 1u) nw = 1;
    if (nw) atomicOr(&g_not_ones_w, 1);
}

// ---------------------------------------------------------------------------
// FAST forward (mask all ones): linear-space recurrence, ONE WARP PER CHAIN.
//   u_t[j] = (sum_i u_{t-1}[i] * E[i][j]) * exp(emit_t[j]) / c_t,  c_t = u_{t-1}[0]
// CTA = 128 threads = 4 warps = 4 independent chains, one warp per SMSP:
// NO CTA barriers in the mainloop — only __syncwarp. Lane l owns states
// {l, l+32, l+64}. E rows 0..47 of the 3 owned columns live in REGISTERS
// (72 u64); E rows 48..95 live in shared (16B/lane/quad, conflict-free).
// u is broadcast from shared via LDS.128. log(c_t) deferred to a post-loop
// warp reduction over a shared history.
__global__ void __launch_bounds__(128) crf_forward_fast_kernel(
    const float* __restrict__ emissions,
    const float* __restrict__ start_t,
    const float* __restrict__ end_t,
    const float* __restrict__ trans)
{
    const int allones = g_mask_byte ? !g_not_ones_b : !g_not_ones_w;
    if (!allones) return;

    const int tid  = threadIdx.x;
    const int w    = tid >> 5;          // warp = chain 0..3
    const int lane = tid & 31;
    const int b    = blockIdx.x * 4 + w;
    const int s0 = lane, s1 = lane + 32, s2 = lane + 64;

    // E rows 48..95 as quads: Esm[q][j] = rows {48+4q .. 51+4q} of column j
    __shared__ __align__(16) ulonglong2 Esm[12][C];
    __shared__ __align__(16) float sh_u[4][2][C];
    __shared__ float sh_hist[4][T];

    // CTA-cooperative init of Esm (1152 entries / 128 threads = 9 each)
    for (int idx = tid; idx < 12 * C; idx += 128) {
        const int q = idx / C, j = idx - q * C;
        const float* tr = trans + (size_t)(48 + 4 * q) * C + j;
        Esm[q][j] = make_ulonglong2(
            pack2(__expf(tr[0]), __expf(tr[C])),
            pack2(__expf(tr[2 * C]), __expf(tr[3 * C])));
    }

    // E rows 0..47 of owned columns in registers: ER[s][k2] = rows {2k2, 2k2+1}
    unsigned long long ER0[24], ER1[24], ER2[24];
#pragma unroll
    for (int k2 = 0; k2 < 24; k2++) {
        const float* tr = trans + (size_t)(2 * k2) * C;
        ER0[k2] = pack2(__expf(tr[s0]), __expf(tr[C + s0]));
        ER1[k2] = pack2(__expf(tr[s1]), __expf(tr[C + s1]));
        ER2[k2] = pack2(__expf(tr[s2]), __expf(tr[C + s2]));
    }

    const float* em0 = emissions + (size_t)b * T * C;
    const float  a00 = start_t[0] + em0[0];

    // u0 (u0[0] = 1 by construction)
    sh_u[w][0][s0] = __expf(start_t[s0] + em0[s0] - a00);
    sh_u[w][0][s1] = __expf(start_t[s1] + em0[s1] - a00);
    sh_u[w][0][s2] = __expf(start_t[s2] + em0[s2] - a00);

    // exp(emit) for t=1, raw emit for t=2, per owned state
    float ee0 = __expf(em0[C + s0]);
    float ee1 = __expf(em0[C + s1]);
    float ee2 = __expf(em0[C + s2]);
    float er0 = em0[2 * C + s0];
    float er1 = em0[2 * C + s1];
    float er2 = em0[2 * C + s2];

    __syncthreads();                    // Esm + u0 visible (one-time)

    int buf = 0;
#pragma unroll 2
    for (int t = 1; t < T; t++) {
        const float4* ub = (const float4*)sh_u[w][buf];

        unsigned long long aA0 = 0ull, aB0 = 0ull;    // state s0
        unsigned long long aA1 = 0ull, aB1 = 0ull;    // state s1
        unsigned long long aA2 = 0ull, aB2 = 0ull;    // state s2
        float c = 0.f, inv = 0.f;

        // rows 0..47 from register E
#pragma unroll
        for (int kb = 0; kb < 12; kb++) {
            const float4 uq = ub[kb];                 // broadcast LDS.128
            const unsigned long long u01 = pack2(uq.x, uq.y);
            const unsigned long long u23 = pack2(uq.z, uq.w);
            if (kb == 0) { c = uq.x; inv = frcp_fast(c); }
            aA0 = ffma2(u01, ER0[2 * kb], aA0);
            aA1 = ffma2(u01, ER1[2 * kb], aA1);
            aA2 = ffma2(u01, ER2[2 * kb], aA2);
            aB0 = ffma2(u23, ER0[2 * kb + 1], aB0);
            aB1 = ffma2(u23, ER1[2 * kb + 1], aB1);
            aB2 = ffma2(u23, ER2[2 * kb + 1], aB2);
        }
        // rows 48..95 from shared E
#pragma unroll
        for (int q = 0; q < 12; q++) {
            const float4 uq = ub[12 + q];             // broadcast LDS.128
            const unsigned long long u01 = pack2(uq.x, uq.y);
            const unsigned long long u23 = pack2(uq.z, uq.w);
            const ulonglong2 e0 = Esm[q][s0];
            const ulonglong2 e1 = Esm[q][s1];
            const ulonglong2 e2 = Esm[q][s2];
            aA0 = ffma2(u01, e0.x, aA0);
            aA1 = ffma2(u01, e1.x, aA1);
            aA2 = ffma2(u01, e2.x, aA2);
            aB0 = ffma2(u23, e0.y, aB0);
            aB1 = ffma2(u23, e1.y, aB1);
            aB2 = ffma2(u23, e2.y, aB2);
        }

        float l0, h0, l1, h1, l2, h2;
        unpack2(fadd2(aA0, aB0), l0, h0);
        unpack2(fadd2(aA1, aB1), l1, h1);
        unpack2(fadd2(aA2, aB2), l2, h2);
        const float d0 = l0 + h0, d1 = l1 + h1, d2 = l2 + h2;

        float* un = sh_u[w][buf ^ 1];
        un[s0] = d0 * (ee0 * inv);
        un[s1] = d1 * (ee1 * inv);
        un[s2] = d2 * (ee2 * inv);
        if (lane == 0) sh_hist[w][t] = c;

        // rotate emission prefetch (off critical path)
        ee0 = __expf(er0); ee1 = __expf(er1); ee2 = __expf(er2);
        if (t + 2 < T) {
            const float* ep = em0 + (size_t)(t + 2) * C;
            er0 = ep[s0]; er1 = ep[s1]; er2 = ep[s2];
        }

        buf ^= 1;
        __syncwarp();                   // order STS -> next-step LDS (warp-local)
    }

    // log_den[b] = a00 + sum_t log(c_t) + log( sum_j u_T[j] * exp(end[j]) )
    const float* uf = sh_u[w][buf];
    float pe = uf[s0] * __expf(end_t[s0])
             + uf[s1] * __expf(end_t[s1])
             + uf[s2] * __expf(end_t[s2]);
    float pl = 0.0f;
    for (int tt = 1 + lane; tt < T; tt += 32) pl += __logf(sh_hist[w][tt]);
#pragma unroll
    for (int off = 16; off > 0; off >>= 1) {
        pe += __shfl_xor_sync(0xffffffffu, pe, off);
        pl += __shfl_xor_sync(0xffffffffu, pl, off);
    }
    if (lane == 0) g_den[b] = a00 + pl + __logf(pe);
}

// ---------------------------------------------------------------------------
// FALLBACK forward (general mask): log-space, shifted lse.
__global__ void __launch_bounds__(384, 1) crf_forward_gen_kernel(
    const float* __restrict__ emissions,
    const unsigned char* __restrict__ mask,
    const float* __restrict__ start_t,
    const float* __restrict__ end_t,
    const float* __restrict__ trans)
{
    const int allones = g_mask_byte ? !g_not_ones_b : !g_not_ones_w;
    if (allones) return;

    const int tid  = threadIdx.x;
    const int sub  = tid / C;
    const int j    = tid - sub * C;
    const int wsub = j >> 5;
    const int lane = j & 31;
    const int b    = blockIdx.x * 4 + sub;
    const int ms   = g_mask_byte ? 1 : 4;

    __shared__ __align__(16) float sh_p[2][4][C];
    __shared__ float sh_m[2][4];
    __shared__ float sh_r[4][4];

    unsigned long long E2[C / 2];
    {
        const float* tb = trans + j;
#pragma unroll
        for (int k = 0; k < C / 2; k++)
            E2[k] = pack2(__expf(tb[(2 * k) * C]), __expf(tb[(2 * k + 1) * C]));
    }

    const float* em = emissions + (size_t)b * T * C + j;
    const unsigned char* mk = mask + (size_t)b * T * ms;

    float alpha = start_t[j] + em[0];
    float m = start_t[0] + emissions[(size_t)b * T * C];

    float e1 = em[C];
    float e2 = em[2 * (size_t)C];
    unsigned char k1 = mk[1 * ms];
    unsigned char k2 = mk[2 * ms];

    int buf = 0;
    for (int t = 1; t < T; t++, buf ^= 1) {
        sh_p[buf][sub][j] = __expf(alpha - m);
        if (j == 0) sh_m[buf][sub] = alpha;
        __syncthreads();

        const ulonglong2* p2 = (const ulonglong2*)sh_p[buf][sub];
        unsigned long long a0 = 0ull, a1 = 0ull;
#pragma unroll
        for (int i = 0; i < C / 4; i++) {
            const ulonglong2 v = p2[i];
            a0 = ffma2(v.x, E2[2 * i + 0], a0);
            a1 = ffma2(v.y, E2[2 * i + 1], a1);
        }
        float lo, hi;
        unpack2(fadd2(a0, a1), lo, hi);
        const float acc = lo + hi;

        const float e_cur = e1;
        const unsigned char mc = k1;
        e1 = e2; k1 = k2;
        if (t + 2 < T) { e2 = em[(size_t)(t + 2) * C]; k2 = mk[(size_t)(t + 2) * ms]; }

        const float na = e_cur + m + __logf(acc);
        alpha = mc ? na : alpha;
        m = sh_m[buf][sub];
    }

    const float v = alpha + end_t[j];
    float wm = v;
    wm = fmaxf(wm, __shfl_xor_sync(0xffffffffu, wm, 16));
    wm = fmaxf(wm, __shfl_xor_sync(0xffffffffu, wm, 8));
    wm = fmaxf(wm, __shfl_xor_sync(0xffffffffu, wm, 4));
    wm = fmaxf(wm, __shfl_xor_sync(0xffffffffu, wm, 2));
    wm = fmaxf(wm, __shfl_xor_sync(0xffffffffu, wm, 1));
    if (lane == 0) sh_r[sub][wsub] = wm;
    __syncthreads();
    const float mf = fmaxf(fmaxf(sh_r[sub][0], sh_r[sub][1]), sh_r[sub][2]);
    __syncthreads();

    float pv = __expf(v - mf);
    pv += __shfl_xor_sync(0xffffffffu, pv, 16);
    pv += __shfl_xor_sync(0xffffffffu, pv, 8);
    pv += __shfl_xor_sync(0xffffffffu, pv, 4);
    pv += __shfl_xor_sync(0xffffffffu, pv, 2);
    pv += __shfl_xor_sync(0xffffffffu, pv, 1);
    if (lane == 0) sh_r[sub][wsub] = pv;
    __syncthreads();
    if (j == 0)
        g_den[b] = mf + __logf(sh_r[sub][0] + sh_r[sub][1] + sh_r[sub][2]);
}

// ---------------------------------------------------------------------------
// Numerator (path score): one CTA per batch element.
__global__ void __launch_bounds__(128) crf_score_kernel(
    const float* __restrict__ emissions,
    const void* __restrict__ tags_raw,
    const unsigned char* __restrict__ mask,
    const float* __restrict__ start_t,
    const float* __restrict__ end_t,
    const float* __restrict__ trans)
{
    const int b = blockIdx.x;
    const int tid = threadIdx.x;
    const int is32 = g_tag_any;
    const int ms = g_mask_byte ? 1 : 4;

    const int* tg32 = (const int*)tags_raw + (size_t)b * T;
    const long long* tg64 = (const long long*)tags_raw + (size_t)b * T;
    const unsigned char* mk = mask + (size_t)b * T * ms;
    const float* eb = emissions + (size_t)b * T * C;

    float sacc = 0.f;
    int len = 0;
    for (int t = tid; t < T; t += 128) {
        const int mt = mk[(size_t)t * ms] ? 1 : 0;
        len += mt;
        if (t >= 1 && mt) {
            const int ct = is32 ? tg32[t] : (int)tg64[t];
            const int pt = is32 ? tg32[t - 1] : (int)tg64[t - 1];
            sacc += eb[(size_t)t * C + ct] + trans[pt * C + ct];
        }
    }

    __shared__ float rs[128];
    __shared__ int   rl[128];
    rs[tid] = sacc;
    rl[tid] = len;
    __syncthreads();
#pragma unroll
    for (int off = 64; off > 0; off >>= 1) {
        if (tid < off) { rs[tid] += rs[tid + off]; rl[tid] += rl[tid + off]; }
        __syncthreads();
    }
    if (tid == 0) {
        const int t0    = is32 ? tg32[0] : (int)tg64[0];
        const int tlast = is32 ? tg32[rl[0] - 1] : (int)tg64[rl[0] - 1];
        g_num[b] = rs[0] + start_t[t0] + eb[t0] + end_t[tlast];
    }
}

// Mean over batch of (log_den - log_num).
__global__ void __launch_bounds__(512) crf_final_kernel(float* __restrict__ out)
{
    const int tid = threadIdx.x;
    __shared__ float r[512];
    r[tid] = g_den[tid] - g_num[tid];
    __syncthreads();
#pragma unroll
    for (int off = 256; off > 0; off >>= 1) {
        if (tid < off) r[tid] += r[tid + off];
        __syncthreads();
    }
    if (tid == 0) out[0] = r[0] * (1.0f / (float)B);
}

extern "C" void kernel_launch(void* const* d_in, const int* in_sizes, int n_in,
                              void* d_out, int out_size)
{
    const float*         emissions = (const float*)d_in[0];
    const void*          tags      = d_in[1];
    const unsigned char* mask      = (const unsigned char*)d_in[2];
    const float*         start_t   = (const float*)d_in[3];
    const float*         end_t     = (const float*)d_in[4];
    const float*         trans     = (const float*)d_in[5];
    float* out = (float*)d_out;

    crf_init_kernel<<<1, 1>>>();
    crf_detect_a_kernel<<<64, 256>>>((const int*)tags, (const unsigned int*)mask);
    crf_detect_b_kernel<<<64, 256>>>((const unsigned int*)mask);
    crf_forward_fast_kernel<<<B / 4, 128>>>(emissions, start_t, end_t, trans);
    crf_forward_gen_kernel<<<B / 4, 384>>>(emissions, mask, start_t, end_t, trans);
    crf_score_kernel<<<B, 128>>>(emissions, tags, mask, start_t, end_t, trans);
    crf_final_kernel<<<1, 512>>>(out);
}